// round 14
// baseline (speedup 1.0000x reference)
#include <cuda_runtime.h>
#include <cstdint>

#define SEQ    512
#define BATCH  256
#define NIN    32
#define HID    128
#define NOUT   16
#define FEAT   9              // silu + 8 spline basis
#define K1X    (NIN * FEAT)   // 288
#define K1H    (HID * FEAT)   // 1152
#define XC_ROWS 32

// cluster decomposition
#define CL_SIZE  8            // CTAs per cluster (portable max)
#define NCLUST   16           // clusters; 16*8 = 128 CTAs
#define ROWS_CL  16           // batch rows per cluster (256/16)
#define ICTA     16           // hidden inputs per CTA (128/8)
#define KSLICE   (ICTA * FEAT)          // 144 k-rows per CTA
#define AS_STRIDE 148                   // A row stride (floats); 148*4=592, 16B-aligned
#define REC_SMEM ((KSLICE * HID + ROWS_CL * HID + ROWS_CL * AS_STRIDE) * 4) // 91392 B

typedef unsigned long long u64;

// ---------------- scratch (device globals; no allocation allowed) ----------
__device__ float g_XC[SEQ * BATCH * HID];        // [t][b][o] x-part contribution
__device__ float g_PF[CL_SIZE * BATCH * HID];    // final-step partials [c][b][o]
__device__ float g_W1x[K1X * HID];               // fused layer1 x-part weights
__device__ float g_W1h[K1H * HID];               // fused layer1 h-part weights
__device__ float g_W2[K1H * NOUT];               // fused layer2 weights

// ---------------- packed f32x2 helpers -------------------------------------
__device__ __forceinline__ u64 pack2(float x) {
    u64 r; asm("mov.b64 %0, {%1, %1};" : "=l"(r) : "f"(x)); return r;
}
__device__ __forceinline__ void fma2(u64& d, u64 a, u64 b) {
    asm("fma.rn.f32x2 %0, %1, %2, %0;" : "+l"(d) : "l"(a), "l"(b));
}
__device__ __forceinline__ void unpack2(u64 v, float& lo, float& hi) {
    asm("mov.b64 {%0, %1}, %2;" : "=f"(lo), "=f"(hi) : "l"(v));
}

// ---------------- cluster / DSMEM helpers ----------------------------------
__device__ __forceinline__ uint32_t smem_u32(const void* p) {
    uint32_t a;
    asm("{ .reg .u64 t; cvta.to.shared.u64 t, %1; cvt.u32.u64 %0, t; }"
        : "=r"(a) : "l"(p));
    return a;
}
__device__ __forceinline__ uint32_t mapa_shared(uint32_t addr, uint32_t rank) {
    uint32_t r;
    asm("mapa.shared::cluster.u32 %0, %1, %2;" : "=r"(r) : "r"(addr), "r"(rank));
    return r;
}
__device__ __forceinline__ float ld_dsmem_f32(uint32_t addr) {
    float v;
    asm volatile("ld.shared::cluster.b32 %0, [%1];" : "=f"(v) : "r"(addr));
    return v;
}
__device__ __forceinline__ void cluster_sync_() {
    asm volatile("barrier.cluster.arrive.aligned;" ::: "memory");
    asm volatile("barrier.cluster.wait.aligned;"   ::: "memory");
}

// ---------------- closed-form uniform cubic B-spline -> dense 9 features ---
// Proven in R12 at rel_err 3.8e-7.
__device__ __forceinline__ void kan_feats9(float x, float* f) {
    f[0] = x / (1.0f + __expf(-x));                 // silu
    float p = (x + 8.8f) * 0.625f;                  // 0.625 = 1/1.6 exact
    int j = (p >= 0.0f && p < 11.0f) ? (int)p : -1; // -1 -> all basis zero
    float u = p - (float)j;                         // unused when j < 0
    float v = 1.0f - u;
    float u2 = u * u, u3 = u2 * u;
    const float s6 = 1.0f / 6.0f;
    float w0 = v * v * v * s6;                                  // basis j-3
    float w1 = (3.0f * u3 - 6.0f * u2 + 4.0f) * s6;             // basis j-2
    float w2 = (-3.0f * u3 + 3.0f * u2 + 3.0f * u + 1.0f) * s6; // basis j-1
    float w3 = u3 * s6;                                         // basis j
#pragma unroll
    for (int m = 0; m < 8; m++) {
        float val = 0.0f;
        val = (j == m + 3) ? w0 : val;
        val = (j == m + 2) ? w1 : val;
        val = (j == m + 1) ? w2 : val;
        val = (j == m    ) ? w3 : val;
        f[1 + m] = val;
    }
}

// ---------------- weight fusion --------------------------------------------
__global__ void prep_kernel(const float* __restrict__ coef1, const float* __restrict__ sb1,
                            const float* __restrict__ sp1,   const float* __restrict__ coef2,
                            const float* __restrict__ sb2,   const float* __restrict__ sp2) {
    int idx = blockIdx.x * blockDim.x + threadIdx.x;
    if (idx < (K1X + K1H) * HID) {
        int j = idx >> 7;        // 0..1439
        int o = idx & 127;
        int i = j / FEAT;        // 0..159
        int m = j % FEAT;
        float w = (m == 0) ? sb1[i * HID + o]
                           : coef1[(i * HID + o) * 8 + (m - 1)] * sp1[i * HID + o];
        if (i < NIN) g_W1x[j * HID + o] = w;
        else         g_W1h[(j - K1X) * HID + o] = w;
    }
    if (idx < K1H * NOUT) {
        int j = idx >> 4;
        int o = idx & 15;
        int i = j / FEAT;
        int m = j % FEAT;
        float w = (m == 0) ? sb2[i * NOUT + o]
                           : coef2[(i * NOUT + o) * 8 + (m - 1)] * sp2[i * NOUT + o];
        g_W2[j * NOUT + o] = w;
    }
}

// ---------------- XC precompute: x-part of layer1 for all timesteps --------
__global__ __launch_bounds__(256) void xc_kernel(const float* __restrict__ x) {
    __shared__ float fs[XC_ROWS * 289];   // row-major, 289 = 288 + pad
    int row0 = blockIdx.x * XC_ROWS;
    int tid = threadIdx.x;
#pragma unroll
    for (int q = 0; q < 4; q++) {
        int e = tid + q * 256;            // 1024 (row,input) evals
        int r = e >> 5, i = e & 31;
        int rid = row0 + r;
        int t = rid >> 8, b = rid & 255;
        float xv = x[(b * SEQ + t) * NIN + i];
        float f[FEAT];
        kan_feats9(xv, f);
        float* frow = &fs[r * 289 + i * FEAT];
#pragma unroll
        for (int m = 0; m < FEAT; m++) frow[m] = f[m];
    }
    __syncthreads();
    int tx = tid & 31, ty = tid >> 5;     // 32 col-groups x 8 row-groups
    u64 acc[8];
#pragma unroll
    for (int u = 0; u < 8; u++) acc[u] = 0ull;
#pragma unroll 4
    for (int k = 0; k < K1X; k++) {
        u64 a0 = pack2(fs[(ty * 4 + 0) * 289 + k]);
        u64 a1 = pack2(fs[(ty * 4 + 1) * 289 + k]);
        u64 a2 = pack2(fs[(ty * 4 + 2) * 289 + k]);
        u64 a3 = pack2(fs[(ty * 4 + 3) * 289 + k]);
        ulonglong2 bb = *reinterpret_cast<const ulonglong2*>(&g_W1x[k * HID + tx * 4]);
        fma2(acc[0], a0, bb.x); fma2(acc[1], a0, bb.y);
        fma2(acc[2], a1, bb.x); fma2(acc[3], a1, bb.y);
        fma2(acc[4], a2, bb.x); fma2(acc[5], a2, bb.y);
        fma2(acc[6], a3, bb.x); fma2(acc[7], a3, bb.y);
    }
#pragma unroll
    for (int q = 0; q < 4; q++) {
        int rid = row0 + ty * 4 + q;
        float4 v;
        unpack2(acc[2 * q + 0], v.x, v.y);
        unpack2(acc[2 * q + 1], v.z, v.w);
        *reinterpret_cast<float4*>(&g_XC[rid * HID + tx * 4]) = v;
    }
}

// ---------------- persistent recurrent kernel: cluster edition --------------
// 16 independent clusters of 8 CTAs; each cluster owns 16 batch rows.
// CTA crank holds W1h k-slice [crank*144, +144) in smem (resident) and its
// 16x128 partial D in smem. Per step:
//   phase A: h = XC + sum over 8 remote D tiles (DSMEM), features -> As
//   cluster sync (all D reads done)
//   GEMM 16x128x144 -> new D in own smem
//   cluster sync (new D published)
// No grid-wide barrier; clusters never interact.
__global__ __launch_bounds__(256, 1) __cluster_dims__(CL_SIZE, 1, 1)
void rec_kernel() {
    extern __shared__ float sm[];
    float* Ws = sm;                              // [144][128] weight slice
    float* Ds = sm + KSLICE * HID;               // [16][128] partial output
    float* As = Ds + ROWS_CL * HID;              // [16][148] features (row-major)
    uint32_t crank;
    asm("mov.u32 %0, %%cluster_ctarank;" : "=r"(crank));
    int cl = blockIdx.x >> 3;                    // cluster id 0..15
    int tid = threadIdx.x;

    // load resident weight slice (rows j0..j0+143, all 128 cols)
    {
        const float4* src = reinterpret_cast<const float4*>(g_W1h + (size_t)crank * KSLICE * HID);
        float4* dst = reinterpret_cast<float4*>(Ws);
        for (int idx = tid; idx < KSLICE * HID / 4; idx += 256) dst[idx] = src[idx];
    }

    // DSMEM base of every rank's D tile
    uint32_t dloc = smem_u32(Ds);
    uint32_t dbase[CL_SIZE];
#pragma unroll
    for (int c = 0; c < CL_SIZE; c++) dbase[c] = mapa_shared(dloc, (uint32_t)c);

    // phase-A mapping: thread -> (row r, local input u)
    int r = tid >> 4, u = tid & 15;
    int i = (int)crank * ICTA + u;               // global hidden index
    int b = cl * ROWS_CL + r;                    // global batch row
    uint32_t doff = (uint32_t)(r * HID + i) * 4u;
    // GEMM mapping: thread -> rows {rg*2, rg*2+1}, cols [cg*4, cg*4+4)
    int rg = tid & 7, cg = tid >> 3;
    const float* Arow0 = &As[(rg * 2 + 0) * AS_STRIDE];
    const float* Arow1 = &As[(rg * 2 + 1) * AS_STRIDE];

    float xc_pre = 0.0f;                         // XC[t-1][b][i] prefetched
    for (int t = 0; t < SEQ; t++) {
        // ---- phase A
        float hv = 0.0f;
        if (t > 0) {
            hv = xc_pre;
#pragma unroll
            for (int c = 0; c < CL_SIZE; c++) hv += ld_dsmem_f32(dbase[c] + doff);
        }
        float f[FEAT];
        kan_feats9(hv, f);
        float* frow = &As[r * AS_STRIDE + u * FEAT];
#pragma unroll
        for (int m = 0; m < FEAT; m++) frow[m] = f[m];
        __syncthreads();
        cluster_sync_();                         // D(t-1) reads complete everywhere

        // prefetch XC[t] for next step (hides DRAM latency under GEMM)
        xc_pre = __ldcg(&g_XC[((size_t)t * BATCH + b) * HID + i]);

        // ---- GEMM: D[16][128] = A[16][144] x W[144][128], f32x2 pairs on cols
        u64 acc0 = 0ull, acc1 = 0ull, acc2 = 0ull, acc3 = 0ull;
#pragma unroll 2
        for (int k0 = 0; k0 < KSLICE; k0 += 4) {
            float4 a0 = *reinterpret_cast<const float4*>(Arow0 + k0);
            float4 a1 = *reinterpret_cast<const float4*>(Arow1 + k0);
#define KSTEP(kk, A0C, A1C)                                                        \
            {                                                                      \
                ulonglong2 bb = *reinterpret_cast<const ulonglong2*>(              \
                    &Ws[(k0 + kk) * HID + cg * 4]);                                \
                u64 p0 = pack2(A0C), p1 = pack2(A1C);                              \
                fma2(acc0, p0, bb.x); fma2(acc1, p0, bb.y);                        \
                fma2(acc2, p1, bb.x); fma2(acc3, p1, bb.y);                        \
            }
            KSTEP(0, a0.x, a1.x)
            KSTEP(1, a0.y, a1.y)
            KSTEP(2, a0.z, a1.z)
            KSTEP(3, a0.w, a1.w)
#undef KSTEP
        }
        float4 v0, v1;
        unpack2(acc0, v0.x, v0.y); unpack2(acc1, v0.z, v0.w);
        unpack2(acc2, v1.x, v1.y); unpack2(acc3, v1.z, v1.w);
        if (t < SEQ - 1) {
            *reinterpret_cast<float4*>(&Ds[(rg * 2 + 0) * HID + cg * 4]) = v0;
            *reinterpret_cast<float4*>(&Ds[(rg * 2 + 1) * HID + cg * 4]) = v1;
            __syncthreads();
            cluster_sync_();                     // D(t) published cluster-wide
        } else {
            // final step: export partials to global for out_kernel
            size_t base = ((size_t)crank * BATCH + cl * ROWS_CL + rg * 2) * HID + cg * 4;
            *reinterpret_cast<float4*>(&g_PF[base]) = v0;
            *reinterpret_cast<float4*>(&g_PF[base + HID]) = v1;
        }
    }
}

// ---------------- layer 2 on final hidden state ----------------------------
__global__ __launch_bounds__(128) void out_kernel(float* __restrict__ out) {
    __shared__ float fs[K1H];
    int b = blockIdx.x;
    int tid = threadIdx.x;                       // tid == hidden index i
    float hv = g_XC[((size_t)(SEQ - 1) * BATCH + b) * HID + tid];
#pragma unroll
    for (int s = 0; s < CL_SIZE; s++) hv += g_PF[((size_t)s * BATCH + b) * HID + tid];
    float f[FEAT];
    kan_feats9(hv, f);
#pragma unroll
    for (int m = 0; m < FEAT; m++) fs[tid * FEAT + m] = f[m];
    __syncthreads();
    int o = tid >> 3, part = tid & 7;            // 16 outputs x 8-way split
    float sum = 0.0f;
    for (int j = part; j < K1H; j += 8) sum += fs[j] * g_W2[j * NOUT + o];
    sum += __shfl_down_sync(0xffffffffu, sum, 4, 8);
    sum += __shfl_down_sync(0xffffffffu, sum, 2, 8);
    sum += __shfl_down_sync(0xffffffffu, sum, 1, 8);
    if (part == 0) out[b * NOUT + o] = sum;
}

// ---------------- launch ----------------------------------------------------
extern "C" void kernel_launch(void* const* d_in, const int* in_sizes, int n_in,
                              void* d_out, int out_size) {
    const float* x     = (const float*)d_in[0];
    const float* coef1 = (const float*)d_in[1];
    const float* sb1   = (const float*)d_in[2];
    const float* sp1   = (const float*)d_in[3];
    const float* coef2 = (const float*)d_in[4];
    const float* sb2   = (const float*)d_in[5];
    const float* sp2   = (const float*)d_in[6];
    float* out = (float*)d_out;

    cudaFuncSetAttribute(rec_kernel, cudaFuncAttributeMaxDynamicSharedMemorySize, REC_SMEM);

    prep_kernel<<<((K1X + K1H) * HID + 255) / 256, 256>>>(coef1, sb1, sp1, coef2, sb2, sp2);
    xc_kernel<<<(SEQ * BATCH) / XC_ROWS, 256>>>(x);
    rec_kernel<<<NCLUST * CL_SIZE, 256, REC_SMEM>>>();
    out_kernel<<<BATCH, 128>>>(out);
}

// round 15
// speedup vs baseline: 1.2601x; 1.2601x over previous
#include <cuda_runtime.h>
#include <cstdint>

#define SEQ    512
#define BATCH  256
#define NIN    32
#define HID    128
#define NOUT   16
#define FEAT   9              // silu + 8 spline basis
#define K1X    (NIN * FEAT)   // 288
#define K1H    (HID * FEAT)   // 1152
#define KSPLIT 32             // k-slices (4 hidden inputs each)
#define NBLK   128            // 4 M-tiles x 32 K-slices
#define XC_ROWS 32
#define KSL    36             // k-rows per slice (4 inputs x 9 feats)
#define AS_STRIDE 72          // 64 rows + pad; 72*4B=288 (16B-aligned), 9*72%32==8 -> conflict-free scatter

typedef unsigned long long u64;

// ---------------- scratch (device globals; no allocation allowed) ----------
__device__ float g_XC[SEQ * BATCH * HID];          // [t][b][o] x-part contribution
__device__ float g_P[2][KSPLIT * BATCH * HID];     // [parity][ks][b][o] partials
__device__ float g_W1x[K1X * HID];                 // fused layer1 x-part weights
__device__ float g_W1h[K1H * HID];                 // fused layer1 h-part weights
__device__ float g_W2[K1H * NOUT];                 // fused layer2 weights
__device__ unsigned int g_bar_count;               // monotonic arrivals
__device__ volatile unsigned int g_bar_gen;        // completed step count

// ---------------- packed f32x2 helpers -------------------------------------
__device__ __forceinline__ u64 pack2(float x) {
    u64 r; asm("mov.b64 %0, {%1, %1};" : "=l"(r) : "f"(x)); return r;
}
__device__ __forceinline__ void fma2(u64& d, u64 a, u64 b) {
    asm("fma.rn.f32x2 %0, %1, %2, %0;" : "+l"(d) : "l"(a), "l"(b));
}
__device__ __forceinline__ void unpack2(u64 v, float& lo, float& hi) {
    asm("mov.b64 {%0, %1}, %2;" : "=f"(lo), "=f"(hi) : "l"(v));
}

// ---------------- closed-form uniform cubic B-spline -> dense 9 features ---
// Proven in R12 at rel_err 3.8e-7.
__device__ __forceinline__ void kan_feats9(float x, float* f) {
    f[0] = x / (1.0f + __expf(-x));                 // silu
    float p = (x + 8.8f) * 0.625f;                  // 0.625 = 1/1.6 exact
    int j = (p >= 0.0f && p < 11.0f) ? (int)p : -1; // -1 -> all basis zero
    float u = p - (float)j;                         // unused when j < 0
    float v = 1.0f - u;
    float u2 = u * u, u3 = u2 * u;
    const float s6 = 1.0f / 6.0f;
    float w0 = v * v * v * s6;                                  // basis j-3
    float w1 = (3.0f * u3 - 6.0f * u2 + 4.0f) * s6;             // basis j-2
    float w2 = (-3.0f * u3 + 3.0f * u2 + 3.0f * u + 1.0f) * s6; // basis j-1
    float w3 = u3 * s6;                                         // basis j
#pragma unroll
    for (int m = 0; m < 8; m++) {
        float val = 0.0f;
        val = (j == m + 3) ? w0 : val;
        val = (j == m + 2) ? w1 : val;
        val = (j == m + 1) ? w2 : val;
        val = (j == m    ) ? w3 : val;
        f[1 + m] = val;
    }
}

// ---------------- weight fusion + barrier reset ----------------------------
__global__ void prep_kernel(const float* __restrict__ coef1, const float* __restrict__ sb1,
                            const float* __restrict__ sp1,   const float* __restrict__ coef2,
                            const float* __restrict__ sb2,   const float* __restrict__ sp2) {
    int idx = blockIdx.x * blockDim.x + threadIdx.x;
    if (idx == 0) { g_bar_count = 0u; g_bar_gen = 0u; }   // graph-replay determinism
    if (idx < (K1X + K1H) * HID) {
        int j = idx >> 7;        // 0..1439
        int o = idx & 127;
        int i = j / FEAT;        // 0..159
        int m = j % FEAT;
        float w = (m == 0) ? sb1[i * HID + o]
                           : coef1[(i * HID + o) * 8 + (m - 1)] * sp1[i * HID + o];
        if (i < NIN) g_W1x[j * HID + o] = w;
        else         g_W1h[(j - K1X) * HID + o] = w;
    }
    if (idx < K1H * NOUT) {
        int j = idx >> 4;
        int o = idx & 15;
        int i = j / FEAT;
        int m = j % FEAT;
        float w = (m == 0) ? sb2[i * NOUT + o]
                           : coef2[(i * NOUT + o) * 8 + (m - 1)] * sp2[i * NOUT + o];
        g_W2[j * NOUT + o] = w;
    }
}

// ---------------- XC precompute: x-part of layer1 for all timesteps --------
__global__ __launch_bounds__(256) void xc_kernel(const float* __restrict__ x) {
    __shared__ float fs[XC_ROWS * 289];   // row-major, 289 = 288 + pad
    int row0 = blockIdx.x * XC_ROWS;
    int tid = threadIdx.x;
#pragma unroll
    for (int q = 0; q < 4; q++) {
        int e = tid + q * 256;            // 1024 (row,input) evals
        int r = e >> 5, i = e & 31;
        int rid = row0 + r;
        int t = rid >> 8, b = rid & 255;
        float xv = x[(b * SEQ + t) * NIN + i];
        float f[FEAT];
        kan_feats9(xv, f);
        float* frow = &fs[r * 289 + i * FEAT];
#pragma unroll
        for (int m = 0; m < FEAT; m++) frow[m] = f[m];
    }
    __syncthreads();
    int tx = tid & 31, ty = tid >> 5;     // 32 col-groups x 8 row-groups
    u64 acc[8];
#pragma unroll
    for (int u = 0; u < 8; u++) acc[u] = 0ull;
#pragma unroll 4
    for (int k = 0; k < K1X; k++) {
        u64 a0 = pack2(fs[(ty * 4 + 0) * 289 + k]);
        u64 a1 = pack2(fs[(ty * 4 + 1) * 289 + k]);
        u64 a2 = pack2(fs[(ty * 4 + 2) * 289 + k]);
        u64 a3 = pack2(fs[(ty * 4 + 3) * 289 + k]);
        ulonglong2 bb = *reinterpret_cast<const ulonglong2*>(&g_W1x[k * HID + tx * 4]);
        fma2(acc[0], a0, bb.x); fma2(acc[1], a0, bb.y);
        fma2(acc[2], a1, bb.x); fma2(acc[3], a1, bb.y);
        fma2(acc[4], a2, bb.x); fma2(acc[5], a2, bb.y);
        fma2(acc[6], a3, bb.x); fma2(acc[7], a3, bb.y);
    }
#pragma unroll
    for (int q = 0; q < 4; q++) {
        int rid = row0 + ty * 4 + q;
        float4 v;
        unpack2(acc[2 * q + 0], v.x, v.y);
        unpack2(acc[2 * q + 1], v.z, v.w);
        *reinterpret_cast<float4*>(&g_XC[rid * HID + tx * 4]) = v;
    }
}

// ---------------- grid barrier (PROVEN R8/R12 version — do not modify) -----
__device__ __forceinline__ void grid_barrier(unsigned int target) {
    __threadfence();            // release this thread's P stores
    __syncthreads();
    if (threadIdx.x == 0) {
        unsigned int arrived = atomicAdd(&g_bar_count, 1u) + 1u;
        if (arrived == target * NBLK) {
            g_bar_gen = target;                 // volatile store, L2
        } else {
            while (g_bar_gen < target) { __nanosleep(32); }
        }
    }
    __syncthreads();
}

// ---------------- probe (profiling slot shifter; ~1us, no side effects) ----
__global__ void probe_kernel() {}

// ---------------- persistent recurrent kernel ------------------------------
// 128 blocks = 4 M-tiles(64 rows) x 32 K-slices(4 inputs, 36 k-rows).
// 1 N-tile: each block holds all 128 output cols -> phase A has zero
// redundancy (1 eval/thread chip-wide) and half the L2 partial traffic.
__global__ __launch_bounds__(256, 1) void rec_kernel() {
    __shared__ float As[KSL * AS_STRIDE];  // k-major: As[k*72 + r], 10.1KB
    __shared__ float Bs[KSL * HID];        // W1h slice [36][128], 18KB, resident
    int bid = blockIdx.x;
    int mi  = bid & 3;                     // M-tile
    int ksl = bid >> 2;                    // k-slice 0..31
    int b0 = mi * 64, i0 = ksl * 4, j0 = ksl * KSL;
    int tid = threadIdx.x;
    for (int idx = tid; idx < KSL * HID; idx += 256)
        Bs[idx] = g_W1h[(j0 + (idx >> 7)) * HID + (idx & 127)];
    // GEMM mapping: thread -> rows [ty*4, +4), cols [tx*8, +8)
    int tx = tid & 15, ty = tid >> 4;
    // phase-A mapping: thread -> (row rA, local input il)
    int rA = tid >> 2, il = tid & 3;

    for (int t = 0; t < SEQ; t++) {
        // ---- phase A: h[b0+rA, i0+il] = XC + sum of 32 partials; 1 eval
        {
            float hv = 0.0f;
            if (t > 0) {
                int b = b0 + rA;
                const float* __restrict__ xcp = g_XC + (size_t)(t - 1) * BATCH * HID;
                hv = xcp[b * HID + i0 + il];
                const float* __restrict__ Pold = g_P[(t + 1) & 1] + b * HID + i0 + il;
                float s0 = 0.f, s1 = 0.f, s2 = 0.f, s3 = 0.f;
#pragma unroll
                for (int s = 0; s < KSPLIT; s += 4) {
                    s0 += __ldcg(Pold + (size_t)(s + 0) * BATCH * HID);
                    s1 += __ldcg(Pold + (size_t)(s + 1) * BATCH * HID);
                    s2 += __ldcg(Pold + (size_t)(s + 2) * BATCH * HID);
                    s3 += __ldcg(Pold + (size_t)(s + 3) * BATCH * HID);
                }
                hv += (s0 + s1) + (s2 + s3);
            }
            float f[FEAT];
            kan_feats9(hv, f);
            float* col = &As[il * FEAT * AS_STRIDE + rA];
#pragma unroll
            for (int m = 0; m < FEAT; m++) col[m * AS_STRIDE] = f[m];
        }
        __syncthreads();

        // ---- phase B: 64x128x36 GEMM, 4-row x 8-col tile, cols paired f32x2
        u64 acc[16];
#pragma unroll
        for (int u = 0; u < 16; u++) acc[u] = 0ull;
#pragma unroll 4
        for (int k = 0; k < KSL; k++) {
            float4 av = *reinterpret_cast<const float4*>(&As[k * AS_STRIDE + ty * 4]);
            ulonglong2 bA = *reinterpret_cast<const ulonglong2*>(&Bs[k * HID + tx * 8]);
            ulonglong2 bB = *reinterpret_cast<const ulonglong2*>(&Bs[k * HID + tx * 8 + 4]);
            u64 a0 = pack2(av.x), a1 = pack2(av.y), a2 = pack2(av.z), a3 = pack2(av.w);
            fma2(acc[0],  a0, bA.x); fma2(acc[1],  a0, bA.y);
            fma2(acc[2],  a0, bB.x); fma2(acc[3],  a0, bB.y);
            fma2(acc[4],  a1, bA.x); fma2(acc[5],  a1, bA.y);
            fma2(acc[6],  a1, bB.x); fma2(acc[7],  a1, bB.y);
            fma2(acc[8],  a2, bA.x); fma2(acc[9],  a2, bA.y);
            fma2(acc[10], a2, bB.x); fma2(acc[11], a2, bB.y);
            fma2(acc[12], a3, bA.x); fma2(acc[13], a3, bA.y);
            fma2(acc[14], a3, bB.x); fma2(acc[15], a3, bB.y);
        }
        float* __restrict__ Pnew = g_P[t & 1];
#pragma unroll
        for (int q = 0; q < 4; q++) {
            int b = b0 + ty * 4 + q;
            float4 v0, v1;
            unpack2(acc[4 * q + 0], v0.x, v0.y);
            unpack2(acc[4 * q + 1], v0.z, v0.w);
            unpack2(acc[4 * q + 2], v1.x, v1.y);
            unpack2(acc[4 * q + 3], v1.z, v1.w);
            float* dst = &Pnew[((size_t)ksl * BATCH + b) * HID + tx * 8];
            *reinterpret_cast<float4*>(dst)     = v0;
            *reinterpret_cast<float4*>(dst + 4) = v1;
        }
        __syncthreads();                  // all stores issued before arrival
        if (t < SEQ - 1) grid_barrier((unsigned int)(t + 1));
    }
}

// ---------------- layer 2 on final hidden state ----------------------------
__global__ __launch_bounds__(128) void out_kernel(float* __restrict__ out) {
    __shared__ float fs[K1H];
    int b = blockIdx.x;
    int tid = threadIdx.x;                       // tid == hidden index i
    float hv = g_XC[((size_t)(SEQ - 1) * BATCH + b) * HID + tid];
    const float* __restrict__ P = g_P[(SEQ - 1) & 1];
#pragma unroll
    for (int s = 0; s < KSPLIT; s++) hv += P[((size_t)s * BATCH + b) * HID + tid];
    float f[FEAT];
    kan_feats9(hv, f);
#pragma unroll
    for (int m = 0; m < FEAT; m++) fs[tid * FEAT + m] = f[m];
    __syncthreads();
    int o = tid >> 3, part = tid & 7;            // 16 outputs x 8-way split
    float sum = 0.0f;
    for (int j = part; j < K1H; j += 8) sum += fs[j] * g_W2[j * NOUT + o];
    sum += __shfl_down_sync(0xffffffffu, sum, 4, 8);
    sum += __shfl_down_sync(0xffffffffu, sum, 2, 8);
    sum += __shfl_down_sync(0xffffffffu, sum, 1, 8);
    if (part == 0) out[b * NOUT + o] = sum;
}

// ---------------- launch ----------------------------------------------------
extern "C" void kernel_launch(void* const* d_in, const int* in_sizes, int n_in,
                              void* d_out, int out_size) {
    const float* x     = (const float*)d_in[0];
    const float* coef1 = (const float*)d_in[1];
    const float* sb1   = (const float*)d_in[2];
    const float* sp1   = (const float*)d_in[3];
    const float* coef2 = (const float*)d_in[4];
    const float* sb2   = (const float*)d_in[5];
    const float* sp2   = (const float*)d_in[6];
    float* out = (float*)d_out;

    prep_kernel<<<((K1X + K1H) * HID + 255) / 256, 256>>>(coef1, sb1, sp1, coef2, sb2, sp2);
    xc_kernel<<<(SEQ * BATCH) / XC_ROWS, 256>>>(x);
    probe_kernel<<<1, 32>>>();   // shifts the ncu profiled slot onto rec_kernel
    rec_kernel<<<NBLK, 256>>>();
    out_kernel<<<BATCH, 128>>>(out);
}

// round 16
// speedup vs baseline: 1.5917x; 1.2631x over previous
#include <cuda_runtime.h>
#include <cstdint>

#define SEQ    512
#define BATCH  256
#define NIN    32
#define HID    128
#define NOUT   16
#define FEAT   9              // silu + 8 spline basis
#define K1X    (NIN * FEAT)   // 288
#define K1H    (HID * FEAT)   // 1152
#define KSPLIT 16
#define NBLK   128
#define XC_ROWS 32
#define AS_STRIDE 68          // 64 rows + pad (k-major A tile)

typedef unsigned long long u64;

// ---------------- scratch (device globals; no allocation allowed) ----------
__device__ float g_XC[SEQ * BATCH * HID];          // [t][b][o] x-part contribution
__device__ float g_P[2][KSPLIT * BATCH * HID];     // [parity][ks][b][o] partials
__device__ float g_W1x[K1X * HID];                 // fused layer1 x-part weights
__device__ float g_W1h[K1H * HID];                 // fused layer1 h-part weights
__device__ float g_W2[K1H * NOUT];                 // fused layer2 weights
__device__ unsigned int g_bar_count;               // monotonic arrivals
__device__ unsigned int g_bar_gen;                 // completed step count

// ---------------- packed f32x2 helpers -------------------------------------
__device__ __forceinline__ u64 pack2(float x) {
    u64 r; asm("mov.b64 %0, {%1, %1};" : "=l"(r) : "f"(x)); return r;
}
__device__ __forceinline__ void fma2(u64& d, u64 a, u64 b) {
    asm("fma.rn.f32x2 %0, %1, %2, %0;" : "+l"(d) : "l"(a), "l"(b));
}
__device__ __forceinline__ void unpack2(u64 v, float& lo, float& hi) {
    asm("mov.b64 {%0, %1}, %2;" : "=f"(lo), "=f"(hi) : "l"(v));
}

// ---------------- closed-form uniform cubic B-spline -> dense 9 features ---
// Proven in R12 at rel_err 3.8e-7.
__device__ __forceinline__ void kan_feats9(float x, float* f) {
    f[0] = x / (1.0f + __expf(-x));                 // silu
    float p = (x + 8.8f) * 0.625f;                  // 0.625 = 1/1.6 exact
    int j = (p >= 0.0f && p < 11.0f) ? (int)p : -1; // -1 -> all basis zero
    float u = p - (float)j;                         // unused when j < 0
    float v = 1.0f - u;
    float u2 = u * u, u3 = u2 * u;
    const float s6 = 1.0f / 6.0f;
    float w0 = v * v * v * s6;                                  // basis j-3
    float w1 = (3.0f * u3 - 6.0f * u2 + 4.0f) * s6;             // basis j-2
    float w2 = (-3.0f * u3 + 3.0f * u2 + 3.0f * u + 1.0f) * s6; // basis j-1
    float w3 = u3 * s6;                                         // basis j
#pragma unroll
    for (int m = 0; m < 8; m++) {
        float val = 0.0f;
        val = (j == m + 3) ? w0 : val;
        val = (j == m + 2) ? w1 : val;
        val = (j == m + 1) ? w2 : val;
        val = (j == m    ) ? w3 : val;
        f[1 + m] = val;
    }
}

// ---------------- weight fusion + barrier reset ----------------------------
__global__ void prep_kernel(const float* __restrict__ coef1, const float* __restrict__ sb1,
                            const float* __restrict__ sp1,   const float* __restrict__ coef2,
                            const float* __restrict__ sb2,   const float* __restrict__ sp2) {
    int idx = blockIdx.x * blockDim.x + threadIdx.x;
    if (idx == 0) { g_bar_count = 0u; g_bar_gen = 0u; }   // graph-replay determinism
    if (idx < (K1X + K1H) * HID) {
        int j = idx >> 7;        // 0..1439
        int o = idx & 127;
        int i = j / FEAT;        // 0..159
        int m = j % FEAT;
        float w = (m == 0) ? sb1[i * HID + o]
                           : coef1[(i * HID + o) * 8 + (m - 1)] * sp1[i * HID + o];
        if (i < NIN) g_W1x[j * HID + o] = w;
        else         g_W1h[(j - K1X) * HID + o] = w;
    }
    if (idx < K1H * NOUT) {
        int j = idx >> 4;
        int o = idx & 15;
        int i = j / FEAT;
        int m = j % FEAT;
        float w = (m == 0) ? sb2[i * NOUT + o]
                           : coef2[(i * NOUT + o) * 8 + (m - 1)] * sp2[i * NOUT + o];
        g_W2[j * NOUT + o] = w;
    }
}

// ---------------- XC precompute: x-part of layer1 for all timesteps --------
__global__ __launch_bounds__(256) void xc_kernel(const float* __restrict__ x) {
    __shared__ float fs[XC_ROWS * 289];   // row-major, 289 = 288 + pad
    int row0 = blockIdx.x * XC_ROWS;
    int tid = threadIdx.x;
#pragma unroll
    for (int q = 0; q < 4; q++) {
        int e = tid + q * 256;            // 1024 (row,input) evals
        int r = e >> 5, i = e & 31;
        int rid = row0 + r;
        int t = rid >> 8, b = rid & 255;
        float xv = x[(b * SEQ + t) * NIN + i];
        float f[FEAT];
        kan_feats9(xv, f);
        float* frow = &fs[r * 289 + i * FEAT];
#pragma unroll
        for (int m = 0; m < FEAT; m++) frow[m] = f[m];
    }
    __syncthreads();
    int tx = tid & 31, ty = tid >> 5;     // 32 col-groups x 8 row-groups
    u64 acc[8];
#pragma unroll
    for (int u = 0; u < 8; u++) acc[u] = 0ull;
#pragma unroll 4
    for (int k = 0; k < K1X; k++) {
        u64 a0 = pack2(fs[(ty * 4 + 0) * 289 + k]);
        u64 a1 = pack2(fs[(ty * 4 + 1) * 289 + k]);
        u64 a2 = pack2(fs[(ty * 4 + 2) * 289 + k]);
        u64 a3 = pack2(fs[(ty * 4 + 3) * 289 + k]);
        ulonglong2 bb = *reinterpret_cast<const ulonglong2*>(&g_W1x[k * HID + tx * 4]);
        fma2(acc[0], a0, bb.x); fma2(acc[1], a0, bb.y);
        fma2(acc[2], a1, bb.x); fma2(acc[3], a1, bb.y);
        fma2(acc[4], a2, bb.x); fma2(acc[5], a2, bb.y);
        fma2(acc[6], a3, bb.x); fma2(acc[7], a3, bb.y);
    }
#pragma unroll
    for (int q = 0; q < 4; q++) {
        int rid = row0 + ty * 4 + q;
        float4 v;
        unpack2(acc[2 * q + 0], v.x, v.y);
        unpack2(acc[2 * q + 1], v.z, v.w);
        *reinterpret_cast<float4*>(&g_XC[rid * HID + tx * 4]) = v;
    }
}

// ---------------- grid barrier: cooperative-groups-style release/acquire ---
// bar.sync gives CTA-scope happens-before from every thread's P stores to
// thread 0; the acq_rel RMW is cumulative (publishes them at gpu scope and,
// for the last arriver, inherits every other block's release). Publisher
// st.release + waiter ld.acquire complete the chain. This is the exact
// pattern cooperative_groups::grid_group::sync() emits.
__device__ __forceinline__ void grid_barrier(unsigned int target) {
    __syncthreads();
    if (threadIdx.x == 0) {
        unsigned int old;
        asm volatile("atom.add.acq_rel.gpu.global.u32 %0, [%1], 1;"
                     : "=r"(old) : "l"(&g_bar_count));
        if (old + 1u == target * NBLK) {
            asm volatile("st.release.gpu.global.u32 [%0], %1;"
                         :: "l"(&g_bar_gen), "r"(target));
        } else {
            unsigned int g;
            do {
                asm volatile("ld.acquire.gpu.global.u32 %0, [%1];"
                             : "=r"(g) : "l"(&g_bar_gen));
            } while (g < target);
        }
    }
    __syncthreads();
}

// ---------------- probe (profiling slot shifter; ~1us, no side effects) ----
__global__ void probe_kernel() {}

// ---------------- persistent recurrent kernel ------------------------------
// 128 blocks = 4 M-tiles(64 rows) x 2 N-tiles(64 cols) x 16 K-tiles(8 inputs).
// Identical tiling to R12 (proven optimum); stall reduction only.
__global__ __launch_bounds__(256, 1) void rec_kernel() {
    __shared__ float As[72 * AS_STRIDE];   // k-major: As[k*68 + r]
    __shared__ float Bs[72 * 64];          // W1h tile, resident across steps
    int bid = blockIdx.x;
    int ks = bid & 15;
    int ni = (bid >> 4) & 1;
    int mi = bid >> 5;
    int b0 = mi * 64, o0 = ni * 64, i0 = ks * 8, j0 = ks * 72;
    int tid = threadIdx.x;
    for (int idx = tid; idx < 72 * 64; idx += 256)
        Bs[idx] = g_W1h[(j0 + (idx >> 6)) * HID + o0 + (idx & 63)];
    int tx = tid & 15, ty = tid >> 4;
    int rA = tid >> 2, il2 = (tid & 3) * 2;   // phase-A: row rA, inputs il2, il2+1
    const float* __restrict__ xc_addr0 = g_XC + (b0 + rA) * HID + i0 + il2;

    float2 xc_pre = make_float2(0.0f, 0.0f);  // XC[t-1] prefetched last iter
    for (int t = 0; t < SEQ; t++) {
        // ---- phase A: features of h_{t-1}; dense select-based writes
        {
            float hx = 0.0f, hy = 0.0f;
            if (t > 0) {
                hx = xc_pre.x; hy = xc_pre.y;
                int b = b0 + rA;
                const float2* __restrict__ Pold =
                    reinterpret_cast<const float2*>(g_P[(t + 1) & 1]) + (b * HID + i0 + il2) / 2;
#pragma unroll
                for (int s = 0; s < KSPLIT; s++) {
                    float2 p = __ldcg(Pold + s * (BATCH * HID / 2));
                    hx += p.x; hy += p.y;
                }
            }
#pragma unroll
            for (int half = 0; half < 2; half++) {
                float hv = half ? hy : hx;
                float f[FEAT];
                kan_feats9(hv, f);
                float* col = &As[(il2 + half) * FEAT * AS_STRIDE + rA];
#pragma unroll
                for (int m = 0; m < FEAT; m++) col[m * AS_STRIDE] = f[m];
            }
        }
        __syncthreads();

        // prefetch XC[t] (used by phase A of step t+1); hidden under the GEMM
        if (t < SEQ - 1)
            xc_pre = __ldcg(reinterpret_cast<const float2*>(
                         xc_addr0 + (size_t)t * BATCH * HID));

        // ---- phase B: 64x64x72 GEMM, 4x4 tile, cols paired in f32x2
        u64 acc[8];
#pragma unroll
        for (int u = 0; u < 8; u++) acc[u] = 0ull;
#pragma unroll 4
        for (int k = 0; k < 72; k++) {
            float4 av = *reinterpret_cast<const float4*>(&As[k * AS_STRIDE + ty * 4]);
            ulonglong2 bb = *reinterpret_cast<const ulonglong2*>(&Bs[k * 64 + tx * 4]);
            u64 a0 = pack2(av.x), a1 = pack2(av.y), a2 = pack2(av.z), a3 = pack2(av.w);
            fma2(acc[0], a0, bb.x); fma2(acc[1], a0, bb.y);
            fma2(acc[2], a1, bb.x); fma2(acc[3], a1, bb.y);
            fma2(acc[4], a2, bb.x); fma2(acc[5], a2, bb.y);
            fma2(acc[6], a3, bb.x); fma2(acc[7], a3, bb.y);
        }
        float* __restrict__ Pnew = g_P[t & 1];
#pragma unroll
        for (int q = 0; q < 4; q++) {
            int b = b0 + ty * 4 + q;
            float4 v;
            unpack2(acc[2 * q + 0], v.x, v.y);
            unpack2(acc[2 * q + 1], v.z, v.w);
            *reinterpret_cast<float4*>(&Pnew[(ks * BATCH + b) * HID + o0 + tx * 4]) = v;
        }
        if (t < SEQ - 1) grid_barrier((unsigned int)(t + 1));
    }
}

// ---------------- layer 2 on final hidden state ----------------------------
__global__ __launch_bounds__(128) void out_kernel(float* __restrict__ out) {
    __shared__ float fs[K1H];
    int b = blockIdx.x;
    int tid = threadIdx.x;                       // tid == hidden index i
    float hv = g_XC[((size_t)(SEQ - 1) * BATCH + b) * HID + tid];
    const float* __restrict__ P = g_P[(SEQ - 1) & 1];
#pragma unroll
    for (int s = 0; s < KSPLIT; s++) hv += P[((size_t)s * BATCH + b) * HID + tid];
    float f[FEAT];
    kan_feats9(hv, f);
#pragma unroll
    for (int m = 0; m < FEAT; m++) fs[tid * FEAT + m] = f[m];
    __syncthreads();
    int o = tid >> 3, part = tid & 7;            // 16 outputs x 8-way split
    float sum = 0.0f;
    for (int j = part; j < K1H; j += 8) sum += fs[j] * g_W2[j * NOUT + o];
    sum += __shfl_down_sync(0xffffffffu, sum, 4, 8);
    sum += __shfl_down_sync(0xffffffffu, sum, 2, 8);
    sum += __shfl_down_sync(0xffffffffu, sum, 1, 8);
    if (part == 0) out[b * NOUT + o] = sum;
}

// ---------------- launch ----------------------------------------------------
extern "C" void kernel_launch(void* const* d_in, const int* in_sizes, int n_in,
                              void* d_out, int out_size) {
    const float* x     = (const float*)d_in[0];
    const float* coef1 = (const float*)d_in[1];
    const float* sb1   = (const float*)d_in[2];
    const float* sp1   = (const float*)d_in[3];
    const float* coef2 = (const float*)d_in[4];
    const float* sb2   = (const float*)d_in[5];
    const float* sp2   = (const float*)d_in[6];
    float* out = (float*)d_out;

    prep_kernel<<<((K1X + K1H) * HID + 255) / 256, 256>>>(coef1, sb1, sp1, coef2, sb2, sp2);
    xc_kernel<<<(SEQ * BATCH) / XC_ROWS, 256>>>(x);
    probe_kernel<<<1, 32>>>();   // shifts the ncu profiled slot onto rec_kernel
    rec_kernel<<<NBLK, 256>>>();
    out_kernel<<<BATCH, 128>>>(out);
}

// round 17
// speedup vs baseline: 1.7288x; 1.0861x over previous
#include <cuda_runtime.h>
#include <cstdint>

#define SEQ    512
#define BATCH  256
#define NIN    32
#define HID    128
#define NOUT   16
#define FEAT   9              // silu + 8 spline basis
#define K1X    (NIN * FEAT)   // 288
#define K1H    (HID * FEAT)   // 1152
#define KSPLIT 16
#define NBLK   128
#define NGRP   4              // independent barrier groups (one per M-tile)
#define GRP_BLKS 32           // blocks per group
#define XC_ROWS 32
#define AS_STRIDE 68          // 64 rows + pad (k-major A tile)

typedef unsigned long long u64;

// ---------------- scratch (device globals; no allocation allowed) ----------
__device__ float g_XC[SEQ * BATCH * HID];          // [t][b][o] x-part contribution
__device__ float g_P[2][KSPLIT * BATCH * HID];     // [parity][ks][b][o] partials
__device__ float g_W1x[K1X * HID];                 // fused layer1 x-part weights
__device__ float g_W1h[K1H * HID];                 // fused layer1 h-part weights
__device__ float g_W2[K1H * NOUT];                 // fused layer2 weights
// per-group barrier state; index grp*32 -> 128B line separation
__device__ __align__(128) unsigned int g_bar_count[NGRP * 32];
__device__ __align__(128) volatile unsigned int g_bar_gen[NGRP * 32];

// ---------------- packed f32x2 helpers -------------------------------------
__device__ __forceinline__ u64 pack2(float x) {
    u64 r; asm("mov.b64 %0, {%1, %1};" : "=l"(r) : "f"(x)); return r;
}
__device__ __forceinline__ void fma2(u64& d, u64 a, u64 b) {
    asm("fma.rn.f32x2 %0, %1, %2, %0;" : "+l"(d) : "l"(a), "l"(b));
}
__device__ __forceinline__ void unpack2(u64 v, float& lo, float& hi) {
    asm("mov.b64 {%0, %1}, %2;" : "=f"(lo), "=f"(hi) : "l"(v));
}

// ---------------- closed-form uniform cubic B-spline -> dense 9 features ---
// Proven in R12 at rel_err 3.8e-7.
__device__ __forceinline__ void kan_feats9(float x, float* f) {
    f[0] = x / (1.0f + __expf(-x));                 // silu
    float p = (x + 8.8f) * 0.625f;                  // 0.625 = 1/1.6 exact
    int j = (p >= 0.0f && p < 11.0f) ? (int)p : -1; // -1 -> all basis zero
    float u = p - (float)j;                         // unused when j < 0
    float v = 1.0f - u;
    float u2 = u * u, u3 = u2 * u;
    const float s6 = 1.0f / 6.0f;
    float w0 = v * v * v * s6;                                  // basis j-3
    float w1 = (3.0f * u3 - 6.0f * u2 + 4.0f) * s6;             // basis j-2
    float w2 = (-3.0f * u3 + 3.0f * u2 + 3.0f * u + 1.0f) * s6; // basis j-1
    float w3 = u3 * s6;                                         // basis j
#pragma unroll
    for (int m = 0; m < 8; m++) {
        float val = 0.0f;
        val = (j == m + 3) ? w0 : val;
        val = (j == m + 2) ? w1 : val;
        val = (j == m + 1) ? w2 : val;
        val = (j == m    ) ? w3 : val;
        f[1 + m] = val;
    }
}

// ---------------- weight fusion + barrier reset ----------------------------
__global__ void prep_kernel(const float* __restrict__ coef1, const float* __restrict__ sb1,
                            const float* __restrict__ sp1,   const float* __restrict__ coef2,
                            const float* __restrict__ sb2,   const float* __restrict__ sp2) {
    int idx = blockIdx.x * blockDim.x + threadIdx.x;
    if (idx < NGRP) {                               // graph-replay determinism
        g_bar_count[idx * 32] = 0u;
        g_bar_gen[idx * 32] = 0u;
    }
    if (idx < (K1X + K1H) * HID) {
        int j = idx >> 7;        // 0..1439
        int o = idx & 127;
        int i = j / FEAT;        // 0..159
        int m = j % FEAT;
        float w = (m == 0) ? sb1[i * HID + o]
                           : coef1[(i * HID + o) * 8 + (m - 1)] * sp1[i * HID + o];
        if (i < NIN) g_W1x[j * HID + o] = w;
        else         g_W1h[(j - K1X) * HID + o] = w;
    }
    if (idx < K1H * NOUT) {
        int j = idx >> 4;
        int o = idx & 15;
        int i = j / FEAT;
        int m = j % FEAT;
        float w = (m == 0) ? sb2[i * NOUT + o]
                           : coef2[(i * NOUT + o) * 8 + (m - 1)] * sp2[i * NOUT + o];
        g_W2[j * NOUT + o] = w;
    }
}

// ---------------- XC precompute: x-part of layer1 for all timesteps --------
__global__ __launch_bounds__(256) void xc_kernel(const float* __restrict__ x) {
    __shared__ float fs[XC_ROWS * 289];   // row-major, 289 = 288 + pad
    int row0 = blockIdx.x * XC_ROWS;
    int tid = threadIdx.x;
#pragma unroll
    for (int q = 0; q < 4; q++) {
        int e = tid + q * 256;            // 1024 (row,input) evals
        int r = e >> 5, i = e & 31;
        int rid = row0 + r;
        int t = rid >> 8, b = rid & 255;
        float xv = x[(b * SEQ + t) * NIN + i];
        float f[FEAT];
        kan_feats9(xv, f);
        float* frow = &fs[r * 289 + i * FEAT];
#pragma unroll
        for (int m = 0; m < FEAT; m++) frow[m] = f[m];
    }
    __syncthreads();
    int tx = tid & 31, ty = tid >> 5;     // 32 col-groups x 8 row-groups
    u64 acc[8];
#pragma unroll
    for (int u = 0; u < 8; u++) acc[u] = 0ull;
#pragma unroll 4
    for (int k = 0; k < K1X; k++) {
        u64 a0 = pack2(fs[(ty * 4 + 0) * 289 + k]);
        u64 a1 = pack2(fs[(ty * 4 + 1) * 289 + k]);
        u64 a2 = pack2(fs[(ty * 4 + 2) * 289 + k]);
        u64 a3 = pack2(fs[(ty * 4 + 3) * 289 + k]);
        ulonglong2 bb = *reinterpret_cast<const ulonglong2*>(&g_W1x[k * HID + tx * 4]);
        fma2(acc[0], a0, bb.x); fma2(acc[1], a0, bb.y);
        fma2(acc[2], a1, bb.x); fma2(acc[3], a1, bb.y);
        fma2(acc[4], a2, bb.x); fma2(acc[5], a2, bb.y);
        fma2(acc[6], a3, bb.x); fma2(acc[7], a3, bb.y);
    }
#pragma unroll
    for (int q = 0; q < 4; q++) {
        int rid = row0 + ty * 4 + q;
        float4 v;
        unpack2(acc[2 * q + 0], v.x, v.y);
        unpack2(acc[2 * q + 1], v.z, v.w);
        *reinterpret_cast<float4*>(&g_XC[rid * HID + tx * 4]) = v;
    }
}

// ---------------- per-group barrier (R12 mechanics, 32-block domain) -------
// Identical instruction sequence to the proven R8/R12 barrier; only the
// membership changed (32 blocks sharing one M-tile). Release: per-thread
// membar.gl orders P stores to L2 before the L2-serialized atomicAdd; the
// last arriver publishes gen after its RMW returned the full count; waiters
// poll the volatile gen with nanosleep backoff. Readers use __ldcg.
__device__ __forceinline__ void grid_barrier(int grp, unsigned int target) {
    __threadfence();            // release this thread's P stores
    __syncthreads();
    if (threadIdx.x == 0) {
        unsigned int arrived = atomicAdd(&g_bar_count[grp * 32], 1u) + 1u;
        if (arrived == target * GRP_BLKS) {
            g_bar_gen[grp * 32] = target;       // volatile store, L2
        } else {
            while (g_bar_gen[grp * 32] < target) { __nanosleep(32); }
        }
    }
    __syncthreads();
}

// ---------------- probe (profiling slot shifter; ~1us, no side effects) ----
__global__ void probe_kernel() {}

// ---------------- persistent recurrent kernel ------------------------------
// 128 blocks = 4 M-tiles(64 rows) x 2 N-tiles(64 cols) x 16 K-tiles(8 inputs).
// Tiling identical to R12 (proven optimum). Sync is per-M-tile (32 blocks):
// each block reads and writes partials only within its own M-tile's rows.
__global__ __launch_bounds__(256, 1) void rec_kernel() {
    __shared__ float As[72 * AS_STRIDE];   // k-major: As[k*68 + r]
    __shared__ float Bs[72 * 64];          // W1h tile, resident across steps
    int bid = blockIdx.x;
    int ks = bid & 15;
    int ni = (bid >> 4) & 1;
    int mi = bid >> 5;                     // M-tile == barrier group
    int b0 = mi * 64, o0 = ni * 64, i0 = ks * 8, j0 = ks * 72;
    int tid = threadIdx.x;
    for (int idx = tid; idx < 72 * 64; idx += 256)
        Bs[idx] = g_W1h[(j0 + (idx >> 6)) * HID + o0 + (idx & 63)];
    int tx = tid & 15, ty = tid >> 4;
    int rA = tid >> 2, il2 = (tid & 3) * 2;   // phase-A: row rA, inputs il2, il2+1
    const float* __restrict__ xc_addr0 = g_XC + (b0 + rA) * HID + i0 + il2;

    float2 xc_pre = make_float2(0.0f, 0.0f);  // XC[t-1], prefetched last iter
    for (int t = 0; t < SEQ; t++) {
        // ---- phase A: features of h_{t-1}; dense select-based writes
        {
            float hx = 0.0f, hy = 0.0f;
            if (t > 0) {
                hx = xc_pre.x; hy = xc_pre.y;
                int b = b0 + rA;
                const float2* __restrict__ Pold =
                    reinterpret_cast<const float2*>(g_P[(t + 1) & 1]) + (b * HID + i0 + il2) / 2;
#pragma unroll
                for (int s = 0; s < KSPLIT; s++) {
                    float2 p = __ldcg(Pold + s * (BATCH * HID / 2));
                    hx += p.x; hy += p.y;
                }
            }
#pragma unroll
            for (int half = 0; half < 2; half++) {
                float hv = half ? hy : hx;
                float f[FEAT];
                kan_feats9(hv, f);
                float* col = &As[(il2 + half) * FEAT * AS_STRIDE + rA];
#pragma unroll
                for (int m = 0; m < FEAT; m++) col[m * AS_STRIDE] = f[m];
            }
        }
        __syncthreads();

        // prefetch XC[t] (used by phase A of step t+1); hidden under the GEMM
        if (t < SEQ - 1)
            xc_pre = __ldcg(reinterpret_cast<const float2*>(
                         xc_addr0 + (size_t)t * BATCH * HID));

        // ---- phase B: 64x64x72 GEMM, 4x4 tile, cols paired in f32x2
        u64 acc[8];
#pragma unroll
        for (int u = 0; u < 8; u++) acc[u] = 0ull;
#pragma unroll 4
        for (int k = 0; k < 72; k++) {
            float4 av = *reinterpret_cast<const float4*>(&As[k * AS_STRIDE + ty * 4]);
            ulonglong2 bb = *reinterpret_cast<const ulonglong2*>(&Bs[k * 64 + tx * 4]);
            u64 a0 = pack2(av.x), a1 = pack2(av.y), a2 = pack2(av.z), a3 = pack2(av.w);
            fma2(acc[0], a0, bb.x); fma2(acc[1], a0, bb.y);
            fma2(acc[2], a1, bb.x); fma2(acc[3], a1, bb.y);
            fma2(acc[4], a2, bb.x); fma2(acc[5], a2, bb.y);
            fma2(acc[6], a3, bb.x); fma2(acc[7], a3, bb.y);
        }
        float* __restrict__ Pnew = g_P[t & 1];
#pragma unroll
        for (int q = 0; q < 4; q++) {
            int b = b0 + ty * 4 + q;
            float4 v;
            unpack2(acc[2 * q + 0], v.x, v.y);
            unpack2(acc[2 * q + 1], v.z, v.w);
            *reinterpret_cast<float4*>(&Pnew[(ks * BATCH + b) * HID + o0 + tx * 4]) = v;
        }
        __syncthreads();                  // all stores issued before arrival
        if (t < SEQ - 1) grid_barrier(mi, (unsigned int)(t + 1));
    }
}

// ---------------- layer 2 on final hidden state ----------------------------
__global__ __launch_bounds__(128) void out_kernel(float* __restrict__ out) {
    __shared__ float fs[K1H];
    int b = blockIdx.x;
    int tid = threadIdx.x;                       // tid == hidden index i
    float hv = g_XC[((size_t)(SEQ - 1) * BATCH + b) * HID + tid];
    const float* __restrict__ P = g_P[(SEQ - 1) & 1];
#pragma unroll
    for (int s = 0; s < KSPLIT; s++) hv += P[((size_t)s * BATCH + b) * HID + tid];
    float f[FEAT];
    kan_feats9(hv, f);
#pragma unroll
    for (int m = 0; m < FEAT; m++) fs[tid * FEAT + m] = f[m];
    __syncthreads();
    int o = tid >> 3, part = tid & 7;            // 16 outputs x 8-way split
    float sum = 0.0f;
    for (int j = part; j < K1H; j += 8) sum += fs[j] * g_W2[j * NOUT + o];
    sum += __shfl_down_sync(0xffffffffu, sum, 4, 8);
    sum += __shfl_down_sync(0xffffffffu, sum, 2, 8);
    sum += __shfl_down_sync(0xffffffffu, sum, 1, 8);
    if (part == 0) out[b * NOUT + o] = sum;
}

// ---------------- launch ----------------------------------------------------
extern "C" void kernel_launch(void* const* d_in, const int* in_sizes, int n_in,
                              void* d_out, int out_size) {
    const float* x     = (const float*)d_in[0];
    const float* coef1 = (const float*)d_in[1];
    const float* sb1   = (const float*)d_in[2];
    const float* sp1   = (const float*)d_in[3];
    const float* coef2 = (const float*)d_in[4];
    const float* sb2   = (const float*)d_in[5];
    const float* sp2   = (const float*)d_in[6];
    float* out = (float*)d_out;

    prep_kernel<<<((K1X + K1H) * HID + 255) / 256, 256>>>(coef1, sb1, sp1, coef2, sb2, sp2);
    xc_kernel<<<(SEQ * BATCH) / XC_ROWS, 256>>>(x);
    probe_kernel<<<1, 32>>>();   // shifts the ncu profiled slot onto rec_kernel
    rec_kernel<<<NBLK, 256>>>();
    out_kernel<<<BATCH, 128>>>(out);
}